// round 6
// baseline (speedup 1.0000x reference)
#include <cuda_runtime.h>
#include <math.h>

#define LAM 1.0
#define NT 256
#define SLOTS 4   // rows per thread (covers N up to 1024)

// Generator (Schur) algorithm for the Toeplitz Cholesky factor, fused with
// y = L @ (sqrt(D) * z) and cumsum. One CTA per batch.
//
// Displacement generators: u = r (since r[0] == 1 here), v = r with v[0]=0.
// Step n: rho = -v[n]/u0;  c = 1/sqrt(1-rho^2)
//   diagonal:  u0 <- c*(u0 + rho*v[n])            (register recursion)
//   for rows j>n:  (u[j-n], v[j]) <- hyperbolic rotation   (elementwise)
//   column n of L = rotated u  ->  y_d[j] += u_new * w_d[n] (registers)
// No dot products, no shuffles, 1 barrier per step.
__global__ __launch_bounds__(NT, 1)
void fbm_schur(const float* __restrict__ alpha,
               const float* __restrict__ tau,
               const float* __restrict__ diff,
               const float* __restrict__ du,
               float* __restrict__ out,
               int T)
{
    const int N = T - 1;                 // 1023
    extern __shared__ float sh[];
    float* u = sh;                       // [N]   generator 1 (sliding physical idx)
    float* v = u + N;                    // [N]   generator 2 (absolute idx)
    float* w = v + N;                    // [3*N] scaled noise; reused for dx2 later

    const int b   = blockIdx.x;
    const int tid = threadIdx.x;

    const double a  = (double)alpha[b];
    const float  tb = tau[b];
    const float  sd = sqrtf(diff[b]);

    // ---- autocovariance (fp64, one time): r[k] = 0.5((k+1)^a + |k-1|^a - 2k^a), taper
    for (int k = tid; k < N; k += NT) {
        double kp = pow((double)(k + 1), a);
        double km = (k == 1) ? 0.0 : pow((double)(k >= 1 ? k - 1 : 1 - k), a);
        double k0 = (k == 0) ? 0.0 : pow((double)k, a);
        double R  = 0.5 * (kp + km - 2.0 * k0);
        if ((float)k >= tb) R *= exp(-LAM * (double)((float)k - tb));
        float rf = (float)R;             // r[0] == 1 exactly
        u[k] = rf;
        v[k] = (k == 0) ? 0.f : rf;
    }
    const float* dub = du + (size_t)b * N * 3;
    for (int i = tid; i < N * 3; i += NT) w[i] = dub[i] * sd;
    __syncthreads();

    // ---- column 0: L[:,0] = r  ->  init register accumulators
    float y0[SLOTS], y1[SLOTS], y2[SLOTS];
    const float w00 = w[0], w01 = w[1], w02 = w[2];
    #pragma unroll
    for (int s = 0; s < SLOTS; s++) {
        int j = tid + NT * s;
        if (j < N) {
            float uj = u[j];
            y0[s] = uj * w00; y1[s] = uj * w01; y2[s] = uj * w02;
        } else { y0[s] = y1[s] = y2[s] = 0.f; }
    }
    __syncthreads();   // column-0 reads of u complete before step-1 writes

    // ---- main recursion: 1 barrier per step, all scalar state replicated
    float u0 = 1.0f;   // r[0]
    for (int n = 1; n < N; n++) {
        float vn  = v[n];                      // broadcast (written step n-1, never this step)
        float rho = -__fdividef(vn, u0);
        float t   = 1.f - rho * rho;
        float c   = rsqrtf(t);
        c = c * (1.5f - 0.5f * t * c * c);     // Newton refine to ~fp32 full precision
        float crho = c * rho;
        float u0n  = c * (u0 + rho * vn);      // new diagonal L[n,n]
        float wn0 = w[3 * n], wn1 = w[3 * n + 1], wn2 = w[3 * n + 2];

        #pragma unroll
        for (int s = 0; s < SLOTS; s++) {
            int j = tid + NT * s;
            if (j > n && j < N) {
                int   i  = j - n;              // sliding physical index into u
                float uu = u[i], vv = v[j];
                float un  = c * uu + crho * vv;
                float vnw = c * vv + crho * uu;
                u[i] = un; v[j] = vnw;
                y0[s] += un * wn0; y1[s] += un * wn1; y2[s] += un * wn2;
            } else if (j == n) {               // diagonal contribution
                y0[s] += u0n * wn0; y1[s] += u0n * wn1; y2[s] += u0n * wn2;
            }
        }
        u0 = u0n;
        __syncthreads();
    }

    // ---- dump dx registers to smem (reuse u, v, w[0:N]) ----
    #pragma unroll
    for (int s = 0; s < SLOTS; s++) {
        int j = tid + NT * s;
        if (j < N) { u[j] = y0[s]; v[j] = y1[s]; w[j] = y2[s]; }
    }
    __syncthreads();

    // ---- cumsum per dim: warp d scans dim d (chunked + warp scan) ----
    {
        int warp = tid >> 5, lane = tid & 31;
        if (warp < 3) {
            float* p = (warp == 0) ? u : ((warp == 1) ? v : w);
            int chunk = (N + 31) >> 5;
            int lo = lane * chunk;
            int hi = lo + chunk; if (hi > N) hi = N;
            float run = 0.f;
            for (int i = lo; i < hi; i++) { run += p[i]; p[i] = run; }
            float tot = run;
            #pragma unroll
            for (int o = 1; o < 32; o <<= 1) {
                float t2 = __shfl_up_sync(0xffffffffu, tot, o);
                if (lane >= o) tot += t2;
            }
            float off = tot - run;            // exclusive prefix of chunk sums
            for (int i = lo; i < hi; i++) p[i] += off;
        }
    }
    __syncthreads();

    // ---- output: leading zero row + interleaved dims, coalesced ----
    float* ob = out + (size_t)b * T * 3;
    for (int idx = tid; idx < T * 3; idx += NT) {
        int t = idx / 3, d = idx - 3 * t;
        float val = 0.f;
        if (t > 0) {
            int j = t - 1;
            val = (d == 0) ? u[j] : ((d == 1) ? v[j] : w[j]);
        }
        ob[idx] = val;
    }
}

extern "C" void kernel_launch(void* const* d_in, const int* in_sizes, int n_in,
                              void* d_out, int out_size)
{
    const float* alpha = (const float*)d_in[0];
    const float* tau   = (const float*)d_in[1];
    const float* diffu = (const float*)d_in[2];
    const float* du    = (const float*)d_in[3];
    float* out = (float*)d_out;

    const int BS   = in_sizes[0];
    const int duN  = in_sizes[3] / BS;   // (T-1)*dim
    const int outN = out_size / BS;      // T*dim
    const int dim  = outN - duN;         // 3
    const int T    = outN / dim;
    const int N    = T - 1;

    size_t smem = (size_t)(N + N + 3 * N) * sizeof(float);

    cudaFuncSetAttribute(fbm_schur,
                         cudaFuncAttributeMaxDynamicSharedMemorySize, (int)smem);

    fbm_schur<<<BS, NT, smem>>>(alpha, tau, diffu, du, out, T);
}